// round 11
// baseline (speedup 1.0000x reference)
#include <cuda_runtime.h>
#include <cuda_bf16.h>
#include <cstdint>

#define G_NUM 128
#define C_NUM 256
#define N_NODES_C 262144
#define N_TILES 2048
#define GRID_MAIN 148
#define THREADS 512

// Scratch (device globals — no allocation allowed)
__device__ uint32_t g_cent[C_NUM * 64];   // centroids as packed bf16 pairs
__device__ float    g_c_sq[C_NUM];
__device__ float    g_sums[G_NUM * C_NUM];
__device__ int      g_counts[G_NUM];

// ---------------------------------------------------------------------------
// smem layout (bytes) — R8-verified map: dist has its own region.
#define OFF_SA    0         // 128 rows x 272B (bf16 x-tile, padded for ldmatrix)
#define OFF_SB    34816     // 256 rows x 272B (bf16 centroids, padded)
#define OFF_STAGE 104448    // 128 rows x 512B (raw f32 tile, cp.async target)
#define OFF_DIST  169984    // 128 rows x 256B (bf16 dist chunk, XOR-swizzled)
#define OFF_XSQ   202752    // 128 f32
#define OFF_CSQ   203264    // 256 f32
#define OFF_BAT   204288    // 128 i32
#define SMEM_TOTAL 204800
#define SA_STRIDE_B 272

#define CP_COMMIT() asm volatile("cp.async.commit_group;" ::: "memory")
#define CP_WAIT0()  asm volatile("cp.async.wait_group 0;" ::: "memory")

__device__ __forceinline__ float fsqrt_approx(float v) {
    float r; asm("sqrt.approx.f32 %0, %1;" : "=f"(r) : "f"(v)); return r;
}

// ---------------------------------------------------------------------------
// Prep: zero sums+counts, convert centroids to bf16 (+c_sq). grid 256 x 256.
__global__ void prep_kernel(const float* __restrict__ cent) {
    int b = blockIdx.x, t = threadIdx.x;
    if (t < 128) g_sums[b * 128 + t] = 0.f;
    if (b == 0 && t >= 128) g_counts[t - 128] = 0;
    if (t < 32) {
        float4 v = ((const float4*)cent)[b * 32 + t];
        __nv_bfloat162 p0 = __floats2bfloat162_rn(v.x, v.y);
        __nv_bfloat162 p1 = __floats2bfloat162_rn(v.z, v.w);
        g_cent[b * 64 + t * 2]     = *(uint32_t*)&p0;
        g_cent[b * 64 + t * 2 + 1] = *(uint32_t*)&p1;
        float a = __bfloat162float(p0.x), c = __bfloat162float(p0.y);
        float e = __bfloat162float(p1.x), f = __bfloat162float(p1.y);
        float s = a * a + c * c + e * e + f * f;
        #pragma unroll
        for (int off = 16; off; off >>= 1) s += __shfl_down_sync(0xffffffffu, s, off);
        if (t == 0) g_c_sq[b] = s;
    }
}

// ---------------------------------------------------------------------------
// Main: persistent 1 CTA/SM, 512 threads (16 warps, 4M x 4N).
// Per tile: 128 nodes x 256 centroids, K=128, mma.sync m16n8k16 bf16.
// A frags single-buffered, B frags double-buffered (register-safe pipeline).
// ---------------------------------------------------------------------------
#define LOAD_A(ksv, AFR) do {                                                   \
    const uint32_t _ko = (uint32_t)(ksv) * 32;                                  \
    _Pragma("unroll")                                                           \
    for (int _mt = 0; _mt < 2; _mt++) {                                         \
        asm volatile("ldmatrix.sync.aligned.m8n8.x4.shared.b16 {%0,%1,%2,%3}, [%4];\n" \
            : "=r"((AFR)[_mt][0]), "=r"((AFR)[_mt][1]),                         \
              "=r"((AFR)[_mt][2]), "=r"((AFR)[_mt][3])                          \
            : "r"(aAddr[_mt] + _ko));                                           \
    }                                                                           \
} while (0)

#define LOAD_B(ksv, BFR) do {                                                   \
    const uint32_t _ko = (uint32_t)(ksv) * 32;                                  \
    _Pragma("unroll")                                                           \
    for (int _p = 0; _p < 4; _p++) {                                            \
        asm volatile("ldmatrix.sync.aligned.m8n8.x4.shared.b16 {%0,%1,%2,%3}, [%4];\n" \
            : "=r"((BFR)[_p][0]), "=r"((BFR)[_p][1]),                           \
              "=r"((BFR)[_p][2]), "=r"((BFR)[_p][3])                            \
            : "r"(bAddr[_p] + _ko));                                            \
    }                                                                           \
} while (0)

__global__ void __launch_bounds__(THREADS, 1)
centroid_main_kernel(const float* __restrict__ x, const int* __restrict__ batch) {
    extern __shared__ char smem[];
    const uint32_t sbase = (uint32_t)__cvta_generic_to_shared(smem);
    float* sXsq = (float*)(smem + OFF_XSQ);
    float* sCsq = (float*)(smem + OFF_CSQ);
    int*   sBat = (int*)  (smem + OFF_BAT);
    uint32_t* sDistW = (uint32_t*)(smem + OFF_DIST);

    const int tid  = threadIdx.x;
    const int lane = tid & 31;
    const int warp = tid >> 5;
    const int wm = (warp & 3) * 32;     // M band
    const int wn = (warp >> 2) * 64;    // N band
    const int gid = lane >> 2;          // 0..7
    const int kq  = lane & 3;           // 0..3

    // Prologue: prefetch tile0's raw f32 into stage
    int tile = blockIdx.x;
    {
        const char* src = (const char*)(x + (size_t)tile * 16384);
        #pragma unroll
        for (int j = 0; j < 8; j++) {
            int gidx = tid + j * 512;
            asm volatile("cp.async.cg.shared.global [%0], [%1], 16;"
                         :: "r"(sbase + OFF_STAGE + gidx * 16),
                            "l"(src + (size_t)gidx * 16) : "memory");
        }
    }
    CP_COMMIT();

    // Load B once (all 256 centroids), padded layout; + c_sq
    #pragma unroll
    for (int i = 0; i < 32; i++) {
        int idx = tid + i * 512;               // 0..16383
        uint32_t v = g_cent[idx];
        int row = idx >> 6, cp = idx & 63;
        ((uint32_t*)(smem + OFF_SB))[row * 68 + cp] = v;
    }
    if (tid < 256) sCsq[tid] = g_c_sq[tid];

    // ldmatrix per-lane addresses (verified mapping, 272B stride)
    const uint32_t sA_b = sbase + OFF_SA;
    const uint32_t sB_b = sbase + OFF_SB;
    const int i8 = lane >> 3, j8 = lane & 7;
    uint32_t aAddr[2], bAddr[4];
    #pragma unroll
    for (int mt = 0; mt < 2; mt++) {
        int row = wm + mt * 16 + j8 + (i8 & 1) * 8;
        aAddr[mt] = sA_b + row * SA_STRIDE_B + (i8 >> 1) * 16;
    }
    #pragma unroll
    for (int p = 0; p < 4; p++) {
        int row = wn + p * 16 + j8 + (i8 >> 1) * 8;
        bAddr[p] = sB_b + row * SA_STRIDE_B + (i8 & 1) * 16;
    }

    for (; tile < N_TILES; tile += GRID_MAIN) {
        CP_WAIT0();
        __syncthreads();   // stage(t) + (first iter: sB/sCsq) visible

        // ---- Convert stage f32 -> sA bf16 (warp-per-row) + x_sq ----
        #pragma unroll
        for (int k = 0; k < 8; k++) {
            int row = warp + k * 16;
            float4 v = *(const float4*)(smem + OFF_STAGE + row * 512 + lane * 16);
            __nv_bfloat162 p0 = __floats2bfloat162_rn(v.x, v.y);
            __nv_bfloat162 p1 = __floats2bfloat162_rn(v.z, v.w);
            uint2 pk = make_uint2(*(uint32_t*)&p0, *(uint32_t*)&p1);
            *(uint2*)(smem + OFF_SA + row * SA_STRIDE_B + lane * 8) = pk;
            // squares from the QUANTIZED values (exact Gram identity)
            float q0 = __uint_as_float(pk.x << 16);
            float q1 = __uint_as_float(pk.x & 0xffff0000u);
            float q2 = __uint_as_float(pk.y << 16);
            float q3 = __uint_as_float(pk.y & 0xffff0000u);
            float s = fmaf(q0, q0, fmaf(q1, q1, fmaf(q2, q2, q3 * q3)));
            #pragma unroll
            for (int off = 16; off; off >>= 1) s += __shfl_xor_sync(0xffffffffu, s, off);
            if (lane == 0) sXsq[row] = s;
        }
        // batch tile + per-node counts (no prep binary search)
        if (tid < 128) {
            int gv = batch[tile * 128 + tid];
            sBat[tid] = gv;
            atomicAdd(&g_counts[gv], 1);
        }
        __syncthreads();   // sA/sXsq/sBat ready; stage reads complete

        // prefetch next tile into stage (lands during k-loop + epilogue)
        int nxt = tile + GRID_MAIN;
        if (nxt < N_TILES) {
            const char* src = (const char*)(x + (size_t)nxt * 16384);
            #pragma unroll
            for (int j = 0; j < 8; j++) {
                int gidx = tid + j * 512;
                asm volatile("cp.async.cg.shared.global [%0], [%1], 16;"
                             :: "r"(sbase + OFF_STAGE + gidx * 16),
                                "l"(src + (size_t)gidx * 16) : "memory");
            }
        }
        CP_COMMIT();

        // ---- K-loop: 8 ksteps; A single-buffer, B double-buffer ----
        float acc[2][8][4];
        #pragma unroll
        for (int mt = 0; mt < 2; mt++)
            #pragma unroll
            for (int nt = 0; nt < 8; nt++)
                #pragma unroll
                for (int q = 0; q < 4; q++) acc[mt][nt][q] = 0.f;

        uint32_t afr[2][4], bfr[2][4][4];
        LOAD_B(0, bfr[0]);
        #pragma unroll
        for (int ks = 0; ks < 8; ks++) {
            const int cur = ks & 1;
            LOAD_A(ks, afr);
            if (ks < 7) LOAD_B(ks + 1, bfr[cur ^ 1]);
            #pragma unroll
            for (int p = 0; p < 4; p++) {
                #pragma unroll
                for (int half = 0; half < 2; half++) {
                    const int nt = p * 2 + half;
                    const uint32_t b0 = bfr[cur][p][half * 2];
                    const uint32_t b1 = bfr[cur][p][half * 2 + 1];
                    #pragma unroll
                    for (int mt = 0; mt < 2; mt++) {
                        asm volatile(
                            "mma.sync.aligned.m16n8k16.row.col.f32.bf16.bf16.f32 "
                            "{%0,%1,%2,%3}, {%4,%5,%6,%7}, {%8,%9}, {%0,%1,%2,%3};\n"
                            : "+f"(acc[mt][nt][0]), "+f"(acc[mt][nt][1]),
                              "+f"(acc[mt][nt][2]), "+f"(acc[mt][nt][3])
                            : "r"(afr[mt][0]), "r"(afr[mt][1]),
                              "r"(afr[mt][2]), "r"(afr[mt][3]),
                              "r"(b0), "r"(b1));
                    }
                }
            }
        }

        // ---- Epilogue: 2 chunks of 128 centroid cols (R8-verified) ----
        #pragma unroll 1
        for (int ch = 0; ch < 2; ch++) {
            if ((wn >> 7) == ch) {
                const int cl0 = wn & 64;      // 0 or 64 within the 128-col chunk
                #pragma unroll
                for (int mt = 0; mt < 2; mt++) {
                    int r = wm + mt * 16 + gid;
                    float xs0 = sXsq[r], xs1 = sXsq[r + 8];
                    const int xr = (r & 7) << 2;   // same for r and r+8
                    #pragma unroll
                    for (int nt = 0; nt < 8; nt++) {
                        int c = cl0 + nt * 8 + kq * 2;
                        int cg = ch * 128 + c;
                        float cs0 = sCsq[cg], cs1 = sCsq[cg + 1];
                        float d00 = fsqrt_approx(fmaxf(xs0 + cs0 - 2.f * acc[mt][nt][0], 0.f));
                        float d01 = fsqrt_approx(fmaxf(xs0 + cs1 - 2.f * acc[mt][nt][1], 0.f));
                        float d10 = fsqrt_approx(fmaxf(xs1 + cs0 - 2.f * acc[mt][nt][2], 0.f));
                        float d11 = fsqrt_approx(fmaxf(xs1 + cs1 - 2.f * acc[mt][nt][3], 0.f));
                        __nv_bfloat162 h0 = __floats2bfloat162_rn(d00, d01);
                        __nv_bfloat162 h1 = __floats2bfloat162_rn(d10, d11);
                        int cp = c >> 1;
                        sDistW[r * 64 + (cp ^ xr)]       = *(uint32_t*)&h0;
                        sDistW[(r + 8) * 64 + (cp ^ xr)] = *(uint32_t*)&h1;
                    }
                }
            }
            __syncthreads();
            // segmented per-colpair reduction: 512 thr = 64 colpairs x 8 rowgroups
            {
                const int cp  = tid & 63;
                const int rb  = (tid >> 6) * 16;
                float a0 = 0.f, a1 = 0.f;
                int curg = sBat[rb];
                const int colg = ch * 128 + cp * 2;
                #pragma unroll 4
                for (int r = rb; r < rb + 16; r++) {
                    int gg = sBat[r];
                    if (gg != curg) {
                        atomicAdd(&g_sums[curg * C_NUM + colg], a0);
                        atomicAdd(&g_sums[curg * C_NUM + colg + 1], a1);
                        a0 = a1 = 0.f; curg = gg;
                    }
                    uint32_t u = sDistW[r * 64 + (cp ^ ((r & 7) << 2))];
                    __nv_bfloat162 h = *(__nv_bfloat162*)&u;
                    a0 += __bfloat162float(h.x);
                    a1 += __bfloat162float(h.y);
                }
                atomicAdd(&g_sums[curg * C_NUM + colg], a0);
                atomicAdd(&g_sums[curg * C_NUM + colg + 1], a1);
            }
            __syncthreads();
        }
    }
}

// ---------------------------------------------------------------------------
__global__ void finalize_kernel(float* __restrict__ out) {
    int g = blockIdx.x, c = threadIdx.x;
    float cnt = (float)(g_counts[g] > 1 ? g_counts[g] : 1);
    out[g * C_NUM + c] = g_sums[g * C_NUM + c] / cnt;
}

// ---------------------------------------------------------------------------
extern "C" void kernel_launch(void* const* d_in, const int* in_sizes, int n_in,
                              void* d_out, int out_size) {
    const float* x     = (const float*)d_in[0];
    const int*   batch = (const int*)d_in[1];
    const float* cent  = (const float*)d_in[2];
    float* out = (float*)d_out;

    cudaFuncSetAttribute(centroid_main_kernel,
                         cudaFuncAttributeMaxDynamicSharedMemorySize, SMEM_TOTAL);

    prep_kernel<<<256, 256>>>(cent);
    centroid_main_kernel<<<GRID_MAIN, THREADS, SMEM_TOTAL>>>(x, batch);
    finalize_kernel<<<G_NUM, 256>>>(out);
}

// round 12
// speedup vs baseline: 1.0141x; 1.0141x over previous
#include <cuda_runtime.h>
#include <cuda_bf16.h>
#include <cstdint>

#define G_NUM 128
#define C_NUM 256
#define N_NODES_C 262144
#define N_TILES 2048
#define GRID_MAIN 148
#define THREADS 512

// Scratch (device globals — no allocation allowed)
__device__ uint32_t g_cent[C_NUM * 64];   // centroids as packed bf16 pairs
__device__ float    g_c_sq[C_NUM];
__device__ float    g_sums[G_NUM * C_NUM];
__device__ int      g_counts[G_NUM];

// ---------------------------------------------------------------------------
// smem layout (bytes) — R8-verified map: dist has its own region.
#define OFF_SA    0         // 128 rows x 272B (bf16 x-tile, padded for ldmatrix)
#define OFF_SB    34816     // 256 rows x 272B (bf16 centroids, padded)
#define OFF_STAGE 104448    // 128 rows x 512B (raw f32 tile, cp.async target)
#define OFF_DIST  169984    // 128 rows x 256B (bf16 dist chunk, XOR-swizzled)
#define OFF_XSQ   202752    // 128 f32
#define OFF_CSQ   203264    // 256 f32
#define OFF_BAT   204288    // 128 i32
#define SMEM_TOTAL 204800
#define SA_STRIDE_B 272

#define CP_COMMIT() asm volatile("cp.async.commit_group;" ::: "memory")
#define CP_WAIT0()  asm volatile("cp.async.wait_group 0;" ::: "memory")

__device__ __forceinline__ float fsqrt_approx(float v) {
    float r; asm("sqrt.approx.f32 %0, %1;" : "=f"(r) : "f"(v)); return r;
}

// ---------------------------------------------------------------------------
// Prep: zero sums+counts, convert centroids to bf16 (+c_sq). grid 256 x 256.
// (R11-measured: 4.7us; counts are accumulated in the main kernel.)
__global__ void prep_kernel(const float* __restrict__ cent) {
    int b = blockIdx.x, t = threadIdx.x;
    if (t < 128) g_sums[b * 128 + t] = 0.f;
    if (b == 0 && t >= 128) g_counts[t - 128] = 0;
    if (t < 32) {
        float4 v = ((const float4*)cent)[b * 32 + t];
        __nv_bfloat162 p0 = __floats2bfloat162_rn(v.x, v.y);
        __nv_bfloat162 p1 = __floats2bfloat162_rn(v.z, v.w);
        g_cent[b * 64 + t * 2]     = *(uint32_t*)&p0;
        g_cent[b * 64 + t * 2 + 1] = *(uint32_t*)&p1;
        float a = __bfloat162float(p0.x), c = __bfloat162float(p0.y);
        float e = __bfloat162float(p1.x), f = __bfloat162float(p1.y);
        float s = a * a + c * c + e * e + f * f;
        #pragma unroll
        for (int off = 16; off; off >>= 1) s += __shfl_down_sync(0xffffffffu, s, off);
        if (t == 0) g_c_sq[b] = s;
    }
}

// ---------------------------------------------------------------------------
// Main: persistent 1 CTA/SM, 512 threads (16 warps, 4M x 4N).
// Per tile: 128 nodes x 256 centroids, K=128, mma.sync m16n8k16 bf16.
// K-loop is the R8-proven single-buffered form (no fragment double-buffering:
// 64 acc regs/thread leaves no headroom — R11 spilled and regressed 1.5x).
// ---------------------------------------------------------------------------
__global__ void __launch_bounds__(THREADS, 1)
centroid_main_kernel(const float* __restrict__ x, const int* __restrict__ batch) {
    extern __shared__ char smem[];
    const uint32_t sbase = (uint32_t)__cvta_generic_to_shared(smem);
    float* sXsq = (float*)(smem + OFF_XSQ);
    float* sCsq = (float*)(smem + OFF_CSQ);
    int*   sBat = (int*)  (smem + OFF_BAT);
    uint32_t* sDistW = (uint32_t*)(smem + OFF_DIST);

    const int tid  = threadIdx.x;
    const int lane = tid & 31;
    const int warp = tid >> 5;
    const int wm = (warp & 3) * 32;     // M band
    const int wn = (warp >> 2) * 64;    // N band
    const int gid = lane >> 2;          // 0..7
    const int kq  = lane & 3;           // 0..3

    // Prologue: prefetch tile0's raw f32 into stage
    int tile = blockIdx.x;
    {
        const char* src = (const char*)(x + (size_t)tile * 16384);
        #pragma unroll
        for (int j = 0; j < 8; j++) {
            int gidx = tid + j * 512;
            asm volatile("cp.async.cg.shared.global [%0], [%1], 16;"
                         :: "r"(sbase + OFF_STAGE + gidx * 16),
                            "l"(src + (size_t)gidx * 16) : "memory");
        }
    }
    CP_COMMIT();

    // Load B once (all 256 centroids), padded layout; + c_sq
    #pragma unroll
    for (int i = 0; i < 32; i++) {
        int idx = tid + i * 512;               // 0..16383
        uint32_t v = g_cent[idx];
        int row = idx >> 6, cp = idx & 63;
        ((uint32_t*)(smem + OFF_SB))[row * 68 + cp] = v;
    }
    if (tid < 256) sCsq[tid] = g_c_sq[tid];

    // ldmatrix per-lane addresses (verified mapping, 272B stride)
    const uint32_t sA_b = sbase + OFF_SA;
    const uint32_t sB_b = sbase + OFF_SB;
    const int i8 = lane >> 3, j8 = lane & 7;
    uint32_t aAddr[2], bAddr[4];
    #pragma unroll
    for (int mt = 0; mt < 2; mt++) {
        int row = wm + mt * 16 + j8 + (i8 & 1) * 8;
        aAddr[mt] = sA_b + row * SA_STRIDE_B + (i8 >> 1) * 16;
    }
    #pragma unroll
    for (int p = 0; p < 4; p++) {
        int row = wn + p * 16 + j8 + (i8 >> 1) * 8;
        bAddr[p] = sB_b + row * SA_STRIDE_B + (i8 & 1) * 16;
    }

    for (; tile < N_TILES; tile += GRID_MAIN) {
        CP_WAIT0();
        __syncthreads();   // stage(t) + (first iter: sB/sCsq) visible

        // ---- Convert stage f32 -> sA bf16 (warp-per-row) + x_sq ----
        #pragma unroll
        for (int k = 0; k < 8; k++) {
            int row = warp + k * 16;
            float4 v = *(const float4*)(smem + OFF_STAGE + row * 512 + lane * 16);
            __nv_bfloat162 p0 = __floats2bfloat162_rn(v.x, v.y);
            __nv_bfloat162 p1 = __floats2bfloat162_rn(v.z, v.w);
            uint2 pk = make_uint2(*(uint32_t*)&p0, *(uint32_t*)&p1);
            *(uint2*)(smem + OFF_SA + row * SA_STRIDE_B + lane * 8) = pk;
            // squares from the QUANTIZED values (exact Gram identity)
            float q0 = __uint_as_float(pk.x << 16);
            float q1 = __uint_as_float(pk.x & 0xffff0000u);
            float q2 = __uint_as_float(pk.y << 16);
            float q3 = __uint_as_float(pk.y & 0xffff0000u);
            float s = fmaf(q0, q0, fmaf(q1, q1, fmaf(q2, q2, q3 * q3)));
            #pragma unroll
            for (int off = 16; off; off >>= 1) s += __shfl_xor_sync(0xffffffffu, s, off);
            if (lane == 0) sXsq[row] = s;
        }
        // batch tile + per-node counts (no prep binary search)
        if (tid < 128) {
            int gv = batch[tile * 128 + tid];
            sBat[tid] = gv;
            atomicAdd(&g_counts[gv], 1);
        }
        __syncthreads();   // sA/sXsq/sBat ready; stage reads complete

        // prefetch next tile into stage (lands during k-loop + epilogue)
        int nxt = tile + GRID_MAIN;
        if (nxt < N_TILES) {
            const char* src = (const char*)(x + (size_t)nxt * 16384);
            #pragma unroll
            for (int j = 0; j < 8; j++) {
                int gidx = tid + j * 512;
                asm volatile("cp.async.cg.shared.global [%0], [%1], 16;"
                             :: "r"(sbase + OFF_STAGE + gidx * 16),
                                "l"(src + (size_t)gidx * 16) : "memory");
            }
        }
        CP_COMMIT();

        // ---- K-loop: 8 ksteps, 6 ldmatrix + 16 mma per step (R8-proven) ----
        float acc[2][8][4];
        #pragma unroll
        for (int mt = 0; mt < 2; mt++)
            #pragma unroll
            for (int nt = 0; nt < 8; nt++)
                #pragma unroll
                for (int q = 0; q < 4; q++) acc[mt][nt][q] = 0.f;

        #pragma unroll
        for (int ks = 0; ks < 8; ks++) {
            const uint32_t koff = ks * 32;
            uint32_t afr[2][4], bfr[4][4];
            #pragma unroll
            for (int mt = 0; mt < 2; mt++) {
                asm volatile(
                    "ldmatrix.sync.aligned.m8n8.x4.shared.b16 {%0,%1,%2,%3}, [%4];\n"
                    : "=r"(afr[mt][0]), "=r"(afr[mt][1]), "=r"(afr[mt][2]), "=r"(afr[mt][3])
                    : "r"(aAddr[mt] + koff));
            }
            #pragma unroll
            for (int p = 0; p < 4; p++) {
                asm volatile(
                    "ldmatrix.sync.aligned.m8n8.x4.shared.b16 {%0,%1,%2,%3}, [%4];\n"
                    : "=r"(bfr[p][0]), "=r"(bfr[p][1]), "=r"(bfr[p][2]), "=r"(bfr[p][3])
                    : "r"(bAddr[p] + koff));
            }
            #pragma unroll
            for (int p = 0; p < 4; p++) {
                #pragma unroll
                for (int half = 0; half < 2; half++) {
                    const int nt = p * 2 + half;
                    const uint32_t b0 = bfr[p][half * 2];
                    const uint32_t b1 = bfr[p][half * 2 + 1];
                    #pragma unroll
                    for (int mt = 0; mt < 2; mt++) {
                        asm volatile(
                            "mma.sync.aligned.m16n8k16.row.col.f32.bf16.bf16.f32 "
                            "{%0,%1,%2,%3}, {%4,%5,%6,%7}, {%8,%9}, {%0,%1,%2,%3};\n"
                            : "+f"(acc[mt][nt][0]), "+f"(acc[mt][nt][1]),
                              "+f"(acc[mt][nt][2]), "+f"(acc[mt][nt][3])
                            : "r"(afr[mt][0]), "r"(afr[mt][1]), "r"(afr[mt][2]), "r"(afr[mt][3]),
                              "r"(b0), "r"(b1));
                    }
                }
            }
        }

        // ---- Epilogue: 2 chunks of 128 centroid cols (R8-verified) ----
        #pragma unroll 1
        for (int ch = 0; ch < 2; ch++) {
            if ((wn >> 7) == ch) {
                const int cl0 = wn & 64;      // 0 or 64 within the 128-col chunk
                #pragma unroll
                for (int mt = 0; mt < 2; mt++) {
                    int r = wm + mt * 16 + gid;
                    float xs0 = sXsq[r], xs1 = sXsq[r + 8];
                    const int xr = (r & 7) << 2;   // same for r and r+8
                    #pragma unroll
                    for (int nt = 0; nt < 8; nt++) {
                        int c = cl0 + nt * 8 + kq * 2;
                        int cg = ch * 128 + c;
                        float cs0 = sCsq[cg], cs1 = sCsq[cg + 1];
                        float d00 = fsqrt_approx(fmaxf(xs0 + cs0 - 2.f * acc[mt][nt][0], 0.f));
                        float d01 = fsqrt_approx(fmaxf(xs0 + cs1 - 2.f * acc[mt][nt][1], 0.f));
                        float d10 = fsqrt_approx(fmaxf(xs1 + cs0 - 2.f * acc[mt][nt][2], 0.f));
                        float d11 = fsqrt_approx(fmaxf(xs1 + cs1 - 2.f * acc[mt][nt][3], 0.f));
                        __nv_bfloat162 h0 = __floats2bfloat162_rn(d00, d01);
                        __nv_bfloat162 h1 = __floats2bfloat162_rn(d10, d11);
                        int cp = c >> 1;
                        sDistW[r * 64 + (cp ^ xr)]       = *(uint32_t*)&h0;
                        sDistW[(r + 8) * 64 + (cp ^ xr)] = *(uint32_t*)&h1;
                    }
                }
            }
            __syncthreads();
            // segmented per-colpair reduction: 512 thr = 64 colpairs x 8 rowgroups
            {
                const int cp  = tid & 63;
                const int rb  = (tid >> 6) * 16;
                float a0 = 0.f, a1 = 0.f;
                int curg = sBat[rb];
                const int colg = ch * 128 + cp * 2;
                #pragma unroll 4
                for (int r = rb; r < rb + 16; r++) {
                    int gg = sBat[r];
                    if (gg != curg) {
                        atomicAdd(&g_sums[curg * C_NUM + colg], a0);
                        atomicAdd(&g_sums[curg * C_NUM + colg + 1], a1);
                        a0 = a1 = 0.f; curg = gg;
                    }
                    uint32_t u = sDistW[r * 64 + (cp ^ ((r & 7) << 2))];
                    __nv_bfloat162 h = *(__nv_bfloat162*)&u;
                    a0 += __bfloat162float(h.x);
                    a1 += __bfloat162float(h.y);
                }
                atomicAdd(&g_sums[curg * C_NUM + colg], a0);
                atomicAdd(&g_sums[curg * C_NUM + colg + 1], a1);
            }
            __syncthreads();
        }
    }
}

// ---------------------------------------------------------------------------
__global__ void finalize_kernel(float* __restrict__ out) {
    int g = blockIdx.x, c = threadIdx.x;
    float cnt = (float)(g_counts[g] > 1 ? g_counts[g] : 1);
    out[g * C_NUM + c] = g_sums[g * C_NUM + c] / cnt;
}

// ---------------------------------------------------------------------------
extern "C" void kernel_launch(void* const* d_in, const int* in_sizes, int n_in,
                              void* d_out, int out_size) {
    const float* x     = (const float*)d_in[0];
    const int*   batch = (const int*)d_in[1];
    const float* cent  = (const float*)d_in[2];
    float* out = (float*)d_out;

    cudaFuncSetAttribute(centroid_main_kernel,
                         cudaFuncAttributeMaxDynamicSharedMemorySize, SMEM_TOTAL);

    prep_kernel<<<256, 256>>>(cent);
    centroid_main_kernel<<<GRID_MAIN, THREADS, SMEM_TOTAL>>>(x, batch);
    finalize_kernel<<<G_NUM, 256>>>(out);
}

// round 13
// speedup vs baseline: 1.0268x; 1.0125x over previous
#include <cuda_runtime.h>
#include <cuda_bf16.h>
#include <cstdint>

#define G_NUM 128
#define C_NUM 256
#define N_NODES_C 262144
#define N_TILES 2048
#define GRID_MAIN 296
#define THREADS 256

// Scratch (device globals — no allocation allowed)
__device__ uint32_t g_cent[C_NUM * 64];   // centroids as packed bf16 pairs
__device__ float    g_c_sq[C_NUM];
__device__ float    g_sums[G_NUM * C_NUM];
__device__ int      g_counts[G_NUM];

// ---------------------------------------------------------------------------
// smem layout (bytes), per CTA (2 CTAs/SM: 2 x 105984 = 211968 <= 227KB)
#define OFF_SA   0         // 128 rows x 272B  bf16 x-tile (ldmatrix-padded)
#define OFF_SB   34816     // 128 rows x 272B  bf16 centroid half (persistent)
#define OFF_DIST 69632     // 128 rows x 272B  bf16 dist tile (stride 68 u32)
#define OFF_XSQ  104448    // 128 f32
#define OFF_CSQ  104960    // 128 f32
#define OFF_BAT  105472    // 128 i32
#define SMEM_TOTAL 105984
#define SA_STRIDE_B 272

__device__ __forceinline__ float fsqrt_approx(float v) {
    float r; asm("sqrt.approx.f32 %0, %1;" : "=f"(r) : "f"(v)); return r;
}

// ---------------------------------------------------------------------------
// Prep: zero sums+counts, convert centroids to bf16 (+c_sq). 4.5us measured.
__global__ void prep_kernel(const float* __restrict__ cent) {
    int b = blockIdx.x, t = threadIdx.x;
    if (t < 128) g_sums[b * 128 + t] = 0.f;
    if (b == 0 && t >= 128) g_counts[t - 128] = 0;
    if (t < 32) {
        float4 v = ((const float4*)cent)[b * 32 + t];
        __nv_bfloat162 p0 = __floats2bfloat162_rn(v.x, v.y);
        __nv_bfloat162 p1 = __floats2bfloat162_rn(v.z, v.w);
        g_cent[b * 64 + t * 2]     = *(uint32_t*)&p0;
        g_cent[b * 64 + t * 2 + 1] = *(uint32_t*)&p1;
        float a = __bfloat162float(p0.x), c = __bfloat162float(p0.y);
        float e = __bfloat162float(p1.x), f = __bfloat162float(p1.y);
        float s = a * a + c * c + e * e + f * f;
        #pragma unroll
        for (int off = 16; off; off >>= 1) s += __shfl_down_sync(0xffffffffu, s, off);
        if (t == 0) g_c_sq[b] = s;
    }
}

// ---------------------------------------------------------------------------
// Main: persistent, 2 CTAs/SM, 256 threads (8 warps, 4M x 2N, warp 32x64).
// Block pair (2t, 2t+1) covers centroid halves {0,1} of the same node tiles
// (adjacent launch order -> co-scheduled -> x-tile L2 reuse, proven in R6).
// B half resident in smem across all tiles. Per tile: 128 nodes x 128 cents.
// ---------------------------------------------------------------------------
__global__ void __launch_bounds__(THREADS, 2)
centroid_main_kernel(const float* __restrict__ x, const int* __restrict__ batch) {
    extern __shared__ char smem[];
    const uint32_t sbase = (uint32_t)__cvta_generic_to_shared(smem);
    float* sXsq = (float*)(smem + OFF_XSQ);
    float* sCsq = (float*)(smem + OFF_CSQ);
    int*   sBat = (int*)  (smem + OFF_BAT);
    uint32_t* sDistW = (uint32_t*)(smem + OFF_DIST);

    const int tid  = threadIdx.x;
    const int lane = tid & 31;
    const int warp = tid >> 5;
    const int by   = blockIdx.x & 1;        // centroid half
    const int pair = blockIdx.x >> 1;       // starting node tile
    const int wm = (warp >> 1) * 32;        // M band
    const int wn = (warp & 1) * 64;         // N band
    const int gid = lane >> 2;              // 0..7
    const int kq  = lane & 3;               // 0..3

    // Load B half once (128 centroids, pre-packed u32 pairs) + c_sq
    {
        const uint32_t* src = g_cent + by * 128 * 64;
        #pragma unroll
        for (int i = 0; i < 32; i++) {
            int idx = tid + i * 256;            // 0..8191
            int row = idx >> 6, cp = idx & 63;
            ((uint32_t*)(smem + OFF_SB))[row * 68 + cp] = src[idx];
        }
        if (tid < 128) sCsq[tid] = g_c_sq[by * 128 + tid];
    }

    // ldmatrix per-lane addresses (R5/R6-verified mapping, 272B stride)
    const uint32_t sA_b = sbase + OFF_SA;
    const uint32_t sB_b = sbase + OFF_SB;
    const int i8 = lane >> 3, j8 = lane & 7;
    uint32_t aAddr[2], bAddr[4];
    #pragma unroll
    for (int mt = 0; mt < 2; mt++) {
        int row = wm + mt * 16 + j8 + (i8 & 1) * 8;
        aAddr[mt] = sA_b + row * SA_STRIDE_B + (i8 >> 1) * 16;
    }
    #pragma unroll
    for (int p = 0; p < 4; p++) {
        int row = wn + p * 16 + j8 + (i8 >> 1) * 8;
        bAddr[p] = sB_b + row * SA_STRIDE_B + (i8 & 1) * 16;
    }

    for (int tile = pair; tile < N_TILES; tile += GRID_MAIN / 2) {
        // ---- Load+convert A tile (f32 LDG -> bf16 STS) + x_sq ----
        {
            const float4* src = (const float4*)(x + (size_t)tile * 16384);
            #pragma unroll
            for (int k = 0; k < 16; k++) {
                int row = k * 8 + warp;
                float4 v = src[row * 32 + lane];
                __nv_bfloat162 p0 = __floats2bfloat162_rn(v.x, v.y);
                __nv_bfloat162 p1 = __floats2bfloat162_rn(v.z, v.w);
                uint2 pk = make_uint2(*(uint32_t*)&p0, *(uint32_t*)&p1);
                *(uint2*)(smem + OFF_SA + row * SA_STRIDE_B + lane * 8) = pk;
                // squares from QUANTIZED values (exact Gram identity)
                float q0 = __uint_as_float(pk.x << 16);
                float q1 = __uint_as_float(pk.x & 0xffff0000u);
                float q2 = __uint_as_float(pk.y << 16);
                float q3 = __uint_as_float(pk.y & 0xffff0000u);
                float s = fmaf(q0, q0, fmaf(q1, q1, fmaf(q2, q2, q3 * q3)));
                #pragma unroll
                for (int off = 16; off; off >>= 1) s += __shfl_xor_sync(0xffffffffu, s, off);
                if (lane == 0) sXsq[row] = s;
            }
            if (tid < 128) {
                int gv = batch[tile * 128 + tid];
                sBat[tid] = gv;
                if (by == 0) atomicAdd(&g_counts[gv], 1);  // count once per node
            }
        }
        __syncthreads();   // S1: sA/sXsq/sBat ready (also first-iter sB/sCsq)

        // ---- K-loop: 8 ksteps, 6 ldmatrix + 16 mma per step (proven) ----
        float acc[2][8][4];
        #pragma unroll
        for (int mt = 0; mt < 2; mt++)
            #pragma unroll
            for (int nt = 0; nt < 8; nt++)
                #pragma unroll
                for (int q = 0; q < 4; q++) acc[mt][nt][q] = 0.f;

        #pragma unroll
        for (int ks = 0; ks < 8; ks++) {
            const uint32_t koff = ks * 32;
            uint32_t afr[2][4], bfr[4][4];
            #pragma unroll
            for (int mt = 0; mt < 2; mt++) {
                asm volatile(
                    "ldmatrix.sync.aligned.m8n8.x4.shared.b16 {%0,%1,%2,%3}, [%4];\n"
                    : "=r"(afr[mt][0]), "=r"(afr[mt][1]), "=r"(afr[mt][2]), "=r"(afr[mt][3])
                    : "r"(aAddr[mt] + koff));
            }
            #pragma unroll
            for (int p = 0; p < 4; p++) {
                asm volatile(
                    "ldmatrix.sync.aligned.m8n8.x4.shared.b16 {%0,%1,%2,%3}, [%4];\n"
                    : "=r"(bfr[p][0]), "=r"(bfr[p][1]), "=r"(bfr[p][2]), "=r"(bfr[p][3])
                    : "r"(bAddr[p] + koff));
            }
            #pragma unroll
            for (int p = 0; p < 4; p++) {
                #pragma unroll
                for (int half = 0; half < 2; half++) {
                    const int nt = p * 2 + half;
                    const uint32_t b0 = bfr[p][half * 2];
                    const uint32_t b1 = bfr[p][half * 2 + 1];
                    #pragma unroll
                    for (int mt = 0; mt < 2; mt++) {
                        asm volatile(
                            "mma.sync.aligned.m16n8k16.row.col.f32.bf16.bf16.f32 "
                            "{%0,%1,%2,%3}, {%4,%5,%6,%7}, {%8,%9}, {%0,%1,%2,%3};\n"
                            : "+f"(acc[mt][nt][0]), "+f"(acc[mt][nt][1]),
                              "+f"(acc[mt][nt][2]), "+f"(acc[mt][nt][3])
                            : "r"(afr[mt][0]), "r"(afr[mt][1]), "r"(afr[mt][2]), "r"(afr[mt][3]),
                              "r"(b0), "r"(b1));
                    }
                }
            }
        }

        // ---- Epilogue: dist (bf16) -> sDistW, all 8 warps, single pass ----
        // write bank-check: u32 addr r*68+cp; lanes (gid,kq) -> banks
        // (4*gid+kq+const) mod 32 = all 32 distinct -> conflict-free.
        #pragma unroll
        for (int mt = 0; mt < 2; mt++) {
            int r = wm + mt * 16 + gid;
            float xs0 = sXsq[r], xs1 = sXsq[r + 8];
            #pragma unroll
            for (int nt = 0; nt < 8; nt++) {
                int c = wn + nt * 8 + kq * 2;          // 0..127 within half
                float cs0 = sCsq[c], cs1 = sCsq[c + 1];
                float d00 = fsqrt_approx(fmaxf(xs0 + cs0 - 2.f * acc[mt][nt][0], 0.f));
                float d01 = fsqrt_approx(fmaxf(xs0 + cs1 - 2.f * acc[mt][nt][1], 0.f));
                float d10 = fsqrt_approx(fmaxf(xs1 + cs0 - 2.f * acc[mt][nt][2], 0.f));
                float d11 = fsqrt_approx(fmaxf(xs1 + cs1 - 2.f * acc[mt][nt][3], 0.f));
                __nv_bfloat162 h0 = __floats2bfloat162_rn(d00, d01);
                __nv_bfloat162 h1 = __floats2bfloat162_rn(d10, d11);
                int cp = c >> 1;
                sDistW[r * 68 + cp]       = *(uint32_t*)&h0;
                sDistW[(r + 8) * 68 + cp] = *(uint32_t*)&h1;
            }
        }
        __syncthreads();   // S2: dist complete; all sA reads (k-loop) done

        // ---- Segmented reduction: 256 thr = 64 colpairs x 4 rowgroups(32) ----
        {
            const int cp = tid & 63;
            const int rb = (tid >> 6) * 32;
            const int colg = by * 128 + cp * 2;
            float a0 = 0.f, a1 = 0.f;
            int curg = sBat[rb];
            #pragma unroll 4
            for (int r = rb; r < rb + 32; r++) {
                int gg = sBat[r];
                if (gg != curg) {
                    atomicAdd(&g_sums[curg * C_NUM + colg], a0);
                    atomicAdd(&g_sums[curg * C_NUM + colg + 1], a1);
                    a0 = a1 = 0.f; curg = gg;
                }
                uint32_t u = sDistW[r * 68 + cp];
                __nv_bfloat162 h = *(__nv_bfloat162*)&u;
                a0 += __bfloat162float(h.x);
                a1 += __bfloat162float(h.y);
            }
            atomicAdd(&g_sums[curg * C_NUM + colg], a0);
            atomicAdd(&g_sums[curg * C_NUM + colg + 1], a1);
        }
        __syncthreads();   // S3: sDist free; safe to overwrite sA next tile
    }
}

// ---------------------------------------------------------------------------
__global__ void finalize_kernel(float* __restrict__ out) {
    int g = blockIdx.x, c = threadIdx.x;
    float cnt = (float)(g_counts[g] > 1 ? g_counts[g] : 1);
    out[g * C_NUM + c] = g_sums[g * C_NUM + c] / cnt;
}

// ---------------------------------------------------------------------------
extern "C" void kernel_launch(void* const* d_in, const int* in_sizes, int n_in,
                              void* d_out, int out_size) {
    const float* x     = (const float*)d_in[0];
    const int*   batch = (const int*)d_in[1];
    const float* cent  = (const float*)d_in[2];
    float* out = (float*)d_out;

    cudaFuncSetAttribute(centroid_main_kernel,
                         cudaFuncAttributeMaxDynamicSharedMemorySize, SMEM_TOTAL);

    prep_kernel<<<256, 256>>>(cent);
    centroid_main_kernel<<<GRID_MAIN, THREADS, SMEM_TOTAL>>>(x, batch);
    finalize_kernel<<<G_NUM, 256>>>(out);
}

// round 14
// speedup vs baseline: 1.0700x; 1.0421x over previous
#include <cuda_runtime.h>
#include <cuda_bf16.h>
#include <cstdint>

#define G_NUM 128
#define C_NUM 256
#define N_NODES_C 262144
#define N_TILES 2048
#define GRID_MAIN 304          // 2 CTAs per SM on 152-SM GB300
#define PAIR_STRIDE (GRID_MAIN / 2)
#define THREADS 256

// Scratch (device globals — no allocation allowed)
__device__ uint32_t g_cent[C_NUM * 64];   // centroids as packed bf16 pairs
__device__ float    g_c_sq[C_NUM];
__device__ float    g_sums[G_NUM * C_NUM];
__device__ int      g_counts[G_NUM];

// ---------------------------------------------------------------------------
// smem layout (bytes), per CTA: 71168 B -> 2 CTAs/SM with wide margin.
#define OFF_SA   0         // 128 rows x 272B  bf16 x-tile (ldmatrix-padded)
#define OFF_SB   34816     // 128 rows x 272B  bf16 centroid half (persistent)
#define OFF_XSQ  69632     // 128 f32
#define OFF_CSQ  70144     // 128 f32
#define OFF_BAT  70656     // 128 i32
#define SMEM_TOTAL 71168
#define SA_STRIDE_B 272

__device__ __forceinline__ float fsqrt_approx(float v) {
    float r; asm("sqrt.approx.f32 %0, %1;" : "=f"(r) : "f"(v)); return r;
}

// ---------------------------------------------------------------------------
// Prep: zero sums+counts, convert centroids to bf16 (+c_sq). ~4.5us measured.
__global__ void prep_kernel(const float* __restrict__ cent) {
    int b = blockIdx.x, t = threadIdx.x;
    if (t < 128) g_sums[b * 128 + t] = 0.f;
    if (b == 0 && t >= 128) g_counts[t - 128] = 0;
    if (t < 32) {
        float4 v = ((const float4*)cent)[b * 32 + t];
        __nv_bfloat162 p0 = __floats2bfloat162_rn(v.x, v.y);
        __nv_bfloat162 p1 = __floats2bfloat162_rn(v.z, v.w);
        g_cent[b * 64 + t * 2]     = *(uint32_t*)&p0;
        g_cent[b * 64 + t * 2 + 1] = *(uint32_t*)&p1;
        float a = __bfloat162float(p0.x), c = __bfloat162float(p0.y);
        float e = __bfloat162float(p1.x), f = __bfloat162float(p1.y);
        float s = a * a + c * c + e * e + f * f;
        #pragma unroll
        for (int off = 16; off; off >>= 1) s += __shfl_down_sync(0xffffffffu, s, off);
        if (t == 0) g_c_sq[b] = s;
    }
}

// ---------------------------------------------------------------------------
// Main: persistent, 2 CTAs/SM, 256 threads (8 warps, 4M x 2N, warp 32x64).
// Block pair (2t, 2t+1) = centroid halves {0,1} of the same node tiles.
// B half resident in smem. Per tile: 128 nodes x 128 centroids, K=128.
// Epilogue: register-space segmented reduction (no dist smem, f32 sums).
// ---------------------------------------------------------------------------
__global__ void __launch_bounds__(THREADS, 2)
centroid_main_kernel(const float* __restrict__ x, const int* __restrict__ batch) {
    extern __shared__ char smem[];
    float* sXsq = (float*)(smem + OFF_XSQ);
    float* sCsq = (float*)(smem + OFF_CSQ);
    int*   sBat = (int*)  (smem + OFF_BAT);

    const int tid  = threadIdx.x;
    const int lane = tid & 31;
    const int warp = tid >> 5;
    const int by   = blockIdx.x & 1;        // centroid half
    const int pair = blockIdx.x >> 1;       // starting node tile
    const int wm = (warp >> 1) * 32;        // M band
    const int wn = (warp & 1) * 64;         // N band
    const int gid = lane >> 2;              // 0..7
    const int kq  = lane & 3;               // 0..3

    // Load B half once (128 centroids, pre-packed u32 pairs) + c_sq
    {
        const uint32_t* src = g_cent + by * 128 * 64;
        #pragma unroll
        for (int i = 0; i < 32; i++) {
            int idx = tid + i * 256;            // 0..8191
            int row = idx >> 6, cp = idx & 63;
            ((uint32_t*)(smem + OFF_SB))[row * 68 + cp] = src[idx];
        }
        if (tid < 128) sCsq[tid] = g_c_sq[by * 128 + tid];
    }

    // ldmatrix per-lane addresses (R5/R6-verified mapping, 272B stride)
    const uint32_t sbase = (uint32_t)__cvta_generic_to_shared(smem);
    const uint32_t sA_b = sbase + OFF_SA;
    const uint32_t sB_b = sbase + OFF_SB;
    const int i8 = lane >> 3, j8 = lane & 7;
    uint32_t aAddr[2], bAddr[4];
    #pragma unroll
    for (int mt = 0; mt < 2; mt++) {
        int row = wm + mt * 16 + j8 + (i8 & 1) * 8;
        aAddr[mt] = sA_b + row * SA_STRIDE_B + (i8 >> 1) * 16;
    }
    #pragma unroll
    for (int p = 0; p < 4; p++) {
        int row = wn + p * 16 + j8 + (i8 >> 1) * 8;
        bAddr[p] = sB_b + row * SA_STRIDE_B + (i8 & 1) * 16;
    }

    for (int tile = pair; tile < N_TILES; tile += PAIR_STRIDE) {
        // ---- Convert: f32 LDG -> bf16 STS (all 8 warps, no shuffles) ----
        {
            const float4* src = (const float4*)(x + (size_t)tile * 16384);
            #pragma unroll
            for (int k = 0; k < 16; k++) {
                int row = k * 8 + warp;
                float4 v = src[row * 32 + lane];
                __nv_bfloat162 p0 = __floats2bfloat162_rn(v.x, v.y);
                __nv_bfloat162 p1 = __floats2bfloat162_rn(v.z, v.w);
                uint2 pk = make_uint2(*(uint32_t*)&p0, *(uint32_t*)&p1);
                *(uint2*)(smem + OFF_SA + row * SA_STRIDE_B + lane * 8) = pk;
            }
        }
        __syncthreads();   // S1: sA stable (first iter: also sB/sCsq)

        // ---- x_sq pass (warps 0-3) + batch/counts; warps 4-7 go to k-loop ----
        if (tid < 128) {
            const uint4* rp = (const uint4*)(smem + OFF_SA + tid * SA_STRIDE_B);
            float s = 0.f;
            #pragma unroll
            for (int j = 0; j < 16; j++) {
                uint4 v = rp[j];
                uint32_t w[4] = {v.x, v.y, v.z, v.w};
                #pragma unroll
                for (int q = 0; q < 4; q++) {
                    float lo = __uint_as_float(w[q] << 16);
                    float hi = __uint_as_float(w[q] & 0xffff0000u);
                    s = fmaf(lo, lo, s); s = fmaf(hi, hi, s);
                }
            }
            sXsq[tid] = s;      // x_sq from QUANTIZED values (exact Gram identity)
            int gv = batch[tile * 128 + tid];
            sBat[tid] = gv;
            if (by == 0) atomicAdd(&g_counts[gv], 1);   // count once per node
        }

        // ---- K-loop: 8 ksteps, 6 ldmatrix + 16 mma per step (R8-proven) ----
        float acc[2][8][4];
        #pragma unroll
        for (int mt = 0; mt < 2; mt++)
            #pragma unroll
            for (int nt = 0; nt < 8; nt++)
                #pragma unroll
                for (int q = 0; q < 4; q++) acc[mt][nt][q] = 0.f;

        #pragma unroll
        for (int ks = 0; ks < 8; ks++) {
            const uint32_t koff = ks * 32;
            uint32_t afr[2][4], bfr[4][4];
            #pragma unroll
            for (int mt = 0; mt < 2; mt++) {
                asm volatile(
                    "ldmatrix.sync.aligned.m8n8.x4.shared.b16 {%0,%1,%2,%3}, [%4];\n"
                    : "=r"(afr[mt][0]), "=r"(afr[mt][1]), "=r"(afr[mt][2]), "=r"(afr[mt][3])
                    : "r"(aAddr[mt] + koff));
            }
            #pragma unroll
            for (int p = 0; p < 4; p++) {
                asm volatile(
                    "ldmatrix.sync.aligned.m8n8.x4.shared.b16 {%0,%1,%2,%3}, [%4];\n"
                    : "=r"(bfr[p][0]), "=r"(bfr[p][1]), "=r"(bfr[p][2]), "=r"(bfr[p][3])
                    : "r"(bAddr[p] + koff));
            }
            #pragma unroll
            for (int p = 0; p < 4; p++) {
                #pragma unroll
                for (int half = 0; half < 2; half++) {
                    const int nt = p * 2 + half;
                    const uint32_t b0 = bfr[p][half * 2];
                    const uint32_t b1 = bfr[p][half * 2 + 1];
                    #pragma unroll
                    for (int mt = 0; mt < 2; mt++) {
                        asm volatile(
                            "mma.sync.aligned.m16n8k16.row.col.f32.bf16.bf16.f32 "
                            "{%0,%1,%2,%3}, {%4,%5,%6,%7}, {%8,%9}, {%0,%1,%2,%3};\n"
                            : "+f"(acc[mt][nt][0]), "+f"(acc[mt][nt][1]),
                              "+f"(acc[mt][nt][2]), "+f"(acc[mt][nt][3])
                            : "r"(afr[mt][0]), "r"(afr[mt][1]), "r"(afr[mt][2]), "r"(afr[mt][3]),
                              "r"(b0), "r"(b1));
                    }
                }
            }
        }
        __syncthreads();   // S2: k-loop sA/sB reads done; sXsq/sBat visible

        // ---- Epilogue: register-space segmented reduction ----
        // Warp band = rows [wm, wm+32). batch sorted, min segment ~2048 >> 32
        // => at most one boundary per band. Bucket rows by (graph != gA),
        // shuffle-reduce over the gid axis, lanes 0-3 fire the atomics.
        {
            const int gA = sBat[wm];
            const int gB = sBat[wm + 31];
            const bool hasB = (gA != gB);
            const int r0 = wm + gid;
            const bool bb0 = sBat[r0]      != gA;
            const bool bb1 = sBat[r0 + 8]  != gA;
            const bool bb2 = sBat[r0 + 16] != gA;
            const bool bb3 = sBat[r0 + 24] != gA;
            const float xs0 = sXsq[r0],      xs1 = sXsq[r0 + 8];
            const float xs2 = sXsq[r0 + 16], xs3 = sXsq[r0 + 24];
            float* sumA = g_sums + gA * C_NUM + by * 128;
            float* sumB = g_sums + gB * C_NUM + by * 128;
            #pragma unroll
            for (int nt = 0; nt < 8; nt++) {
                #pragma unroll
                for (int q = 0; q < 2; q++) {
                    const int c = wn + nt * 8 + kq * 2 + q;
                    const float cs = sCsq[c];
                    float d0 = fsqrt_approx(fmaxf(xs0 + cs - 2.f * acc[0][nt][q],     0.f));
                    float d1 = fsqrt_approx(fmaxf(xs1 + cs - 2.f * acc[0][nt][q + 2], 0.f));
                    float d2 = fsqrt_approx(fmaxf(xs2 + cs - 2.f * acc[1][nt][q],     0.f));
                    float d3 = fsqrt_approx(fmaxf(xs3 + cs - 2.f * acc[1][nt][q + 2], 0.f));
                    float p1 = (bb0 ? d0 : 0.f) + (bb1 ? d1 : 0.f)
                             + (bb2 ? d2 : 0.f) + (bb3 ? d3 : 0.f);
                    float p0 = (d0 + d1 + d2 + d3) - p1;
                    p0 += __shfl_down_sync(0xffffffffu, p0, 16);
                    p0 += __shfl_down_sync(0xffffffffu, p0, 8);
                    p0 += __shfl_down_sync(0xffffffffu, p0, 4);
                    if (hasB) {   // warp-uniform branch
                        p1 += __shfl_down_sync(0xffffffffu, p1, 16);
                        p1 += __shfl_down_sync(0xffffffffu, p1, 8);
                        p1 += __shfl_down_sync(0xffffffffu, p1, 4);
                        if (lane < 4) atomicAdd(&sumB[c], p1);
                    }
                    if (lane < 4) atomicAdd(&sumA[c], p0);
                }
            }
        }
        // no barrier here: epilogue is register/LDS-read only; next convert's
        // sA writes are safe (S2 passed), and sBat/sXsq for tile t+1 are only
        // written after S1(t+1), which all warps reach post-epilogue.
    }
}

// ---------------------------------------------------------------------------
__global__ void finalize_kernel(float* __restrict__ out) {
    int g = blockIdx.x, c = threadIdx.x;
    float cnt = (float)(g_counts[g] > 1 ? g_counts[g] : 1);
    out[g * C_NUM + c] = g_sums[g * C_NUM + c] / cnt;
}

// ---------------------------------------------------------------------------
extern "C" void kernel_launch(void* const* d_in, const int* in_sizes, int n_in,
                              void* d_out, int out_size) {
    const float* x     = (const float*)d_in[0];
    const int*   batch = (const int*)d_in[1];
    const float* cent  = (const float*)d_in[2];
    float* out = (float*)d_out;

    cudaFuncSetAttribute(centroid_main_kernel,
                         cudaFuncAttributeMaxDynamicSharedMemorySize, SMEM_TOTAL);

    prep_kernel<<<256, 256>>>(cent);
    centroid_main_kernel<<<GRID_MAIN, THREADS, SMEM_TOTAL>>>(x, batch);
    finalize_kernel<<<G_NUM, 256>>>(out);
}